// round 14
// baseline (speedup 1.0000x reference)
#include <cuda_runtime.h>
#include <math.h>

#define BATCH 64
#define T 128
#define NS 32
#define MD 8
#define PD 16
#define ST 36      // stride for 32-wide rows (float4-aligned)
#define SP 20      // stride for 16-wide rows (float4-aligned)
#define QVAR 0.01f
#define RVAR 0.01f

#define TBAR(id) asm volatile("bar.sync %0, %1;" :: "r"(id), "r"(256) : "memory")

__device__ __align__(16) float g_muf [BATCH * T * NS];
__device__ __align__(16) float g_mup [BATCH * T * NS];
__device__ __align__(16) float g_Sigf[BATCH * T * NS * NS];
__device__ __align__(16) float g_Sigp[BATCH * T * NS * NS];
__device__ __align__(16) float g_J   [BATCH * T * NS * NS];  // J transposed: [t][k][i] = J[i][k]

struct __align__(16) FwdS {
    float At [NS][ST];   // A^T (k-major)
    float Sig[NS][ST];   // carry Sigma_f
    float T1 [NS][ST];   // (A*Sig)^T
    float Sp [NS][ST];   // Sigma_pred
    float Ct [NS][SP];   // C^T (k-major)
    float W  [NS][SP];   // W = Sp C^T
    float Wt [PD][ST];
    float Kt [PD][ST];
    float S  [PD][SP];
    float B  [NS][MD];
    float mu[NS], mup[NS], r[PD], y[PD], uu[MD];
    float pad[8];
};

struct __align__(16) BwdS {
    float Sig[NS][ST];
    float T1 [NS][ST];
    float Jt[2][NS][ST], Sf[2][NS][ST], Sp[2][NS][ST];
    float muP[2][NS], mufB[2][NS], mupB[2][NS];
    float pad[8];
};

// ============== FORWARD FILTER (2 teams/CTA, 2 batches/team, 6 phases, 4x4 tiles) ==============
__global__ __launch_bounds__(512, 1)
void fwd_kernel(const float* __restrict__ Y, const float* __restrict__ U,
                const float* __restrict__ A, const float* __restrict__ Bm,
                const float* __restrict__ C, const float* __restrict__ mu0,
                const float* __restrict__ Sig0, float* __restrict__ out)
{
    extern __shared__ __align__(16) char dyn[];
    __shared__ unsigned char mR8[36], mC8[36], mR4[10], mC4[10];

    const int tid  = threadIdx.x;
    const int team = tid >> 8, rt = tid & 255;
    const int bar  = 1 + team;
    FwdS* sb = (FwdS*)dyn + team * 2;
    const int b0 = blockIdx.x * 4 + team * 2;      // this team's batches: b0, b0+1
    const int mm = team ? (rt ^ 64) : rt;          // SMSP-disjoint roles

    if (tid == 0) {
        int e = 0;
        for (int r = 0; r < 8; ++r)
            for (int c = r; c < 8; ++c) { mR8[e] = (unsigned char)r; mC8[e] = (unsigned char)c; ++e; }
        e = 0;
        for (int r = 0; r < 4; ++r)
            for (int c = r; c < 4; ++c) { mR4[e] = (unsigned char)r; mC4[e] = (unsigned char)c; ++e; }
    }
    for (int bi = 0; bi < 2; ++bi) {
        FwdS& s = sb[bi];
        const size_t o = (size_t)(b0 + bi) * T;
        const float* A0 = A  + o * NS * NS;
        const float* C0 = C  + o * PD * NS;
        const float* B0 = Bm + o * NS * MD;
        for (int e = rt; e < NS * NS; e += 256) { s.At[e & 31][e >> 5] = A0[e]; s.Sig[e >> 5][e & 31] = Sig0[e]; }
        for (int e = rt; e < PD * NS; e += 256) s.Ct[e & 31][e >> 5] = C0[e];
        s.B[rt >> 3][rt & 7] = B0[rt];
        if (rt < PD) s.y[rt] = Y[o * PD + rt];
        else if (rt < PD + MD) s.uu[rt - PD] = U[o * MD + (rt - PD)];
        if (rt >= 32 && rt < 64) s.mu[rt - 32] = mu0[rt - 32];
    }
    __syncthreads();

    for (int t = 0; t < T; ++t) {

        // --- P1: T1^T = (A*Sig)^T : 64 tiles x 2 batches [0,128) ; mu_p [128,192) ---
        if (mm < 128) {
            const int bi = mm >> 6, q = mm & 63;
            FwdS& s = sb[bi];
            const int i0 = 4 * (q >> 3), j0 = 4 * (q & 7);
            float c[4][4] = {};
            #pragma unroll 8
            for (int k = 0; k < NS; ++k) {
                float4 a  = *(const float4*)&s.At[k][i0];
                float4 bb = *(const float4*)&s.Sig[k][j0];
                c[0][0] += a.x * bb.x; c[0][1] += a.x * bb.y; c[0][2] += a.x * bb.z; c[0][3] += a.x * bb.w;
                c[1][0] += a.y * bb.x; c[1][1] += a.y * bb.y; c[1][2] += a.y * bb.z; c[1][3] += a.y * bb.w;
                c[2][0] += a.z * bb.x; c[2][1] += a.z * bb.y; c[2][2] += a.z * bb.z; c[2][3] += a.z * bb.w;
                c[3][0] += a.w * bb.x; c[3][1] += a.w * bb.y; c[3][2] += a.w * bb.z; c[3][3] += a.w * bb.w;
            }
            #pragma unroll
            for (int m = 0; m < 4; ++m)
                #pragma unroll
                for (int n = 0; n < 4; ++n) s.T1[j0 + n][i0 + m] = c[m][n];
        } else if (mm < 192) {
            const int bi = (mm - 128) >> 5, i = mm & 31;
            FwdS& s = sb[bi];
            float acc = 0.f;
            #pragma unroll 8
            for (int k = 0; k < NS; ++k) acc += s.At[k][i] * s.mu[k];
            #pragma unroll
            for (int k = 0; k < MD; ++k) acc += s.B[i][k] * s.uu[k];
            s.mup[i] = acc;
        }
        TBAR(bar);

        // --- P2: Sp = sym(T1 A^T)+Q : 36 tiles x2 [0,72) ; r [96,128) ; g_mup [128,192) ---
        if (mm < 72) {
            const int bi = mm >= 36, q = mm - 36 * bi;
            FwdS& s = sb[bi];
            const int ti = mR8[q], tj = mC8[q];
            const int i0 = 4 * ti, j0 = 4 * tj;
            float c[4][4] = {};
            #pragma unroll 8
            for (int k = 0; k < NS; ++k) {
                float4 a  = *(const float4*)&s.T1[k][i0];
                float4 bb = *(const float4*)&s.At[k][j0];
                c[0][0] += a.x * bb.x; c[0][1] += a.x * bb.y; c[0][2] += a.x * bb.z; c[0][3] += a.x * bb.w;
                c[1][0] += a.y * bb.x; c[1][1] += a.y * bb.y; c[1][2] += a.y * bb.z; c[1][3] += a.y * bb.w;
                c[2][0] += a.z * bb.x; c[2][1] += a.z * bb.y; c[2][2] += a.z * bb.z; c[2][3] += a.z * bb.w;
                c[3][0] += a.w * bb.x; c[3][1] += a.w * bb.y; c[3][2] += a.w * bb.z; c[3][3] += a.w * bb.w;
            }
            if (ti == tj) {
                #pragma unroll
                for (int m = 0; m < 4; ++m) {
                    c[m][m] += QVAR;
                    #pragma unroll
                    for (int n = m + 1; n < 4; ++n) { float av = 0.5f * (c[m][n] + c[n][m]); c[m][n] = av; c[n][m] = av; }
                }
            }
            #pragma unroll
            for (int m = 0; m < 4; ++m)
                #pragma unroll
                for (int n = 0; n < 4; ++n) {
                    s.Sp[i0 + m][j0 + n] = c[m][n];
                    if (ti != tj) s.Sp[j0 + n][i0 + m] = c[m][n];
                }
        } else if (mm >= 96 && mm < 128) {
            const int bi = (mm - 96) >> 4, i = mm & 15;
            FwdS& s = sb[bi];
            float acc = s.y[i];
            #pragma unroll 8
            for (int k = 0; k < NS; ++k) acc -= s.Ct[k][i] * s.mup[k];
            s.r[i] = acc;
        } else if (mm >= 128 && mm < 192) {
            const int bi = (mm - 128) >> 5, i = mm & 31;
            g_mup[((size_t)(b0 + bi) * T + t) * NS + i] = sb[bi].mup[i];
        }
        TBAR(bar);

        // --- P3: W = Sp C^T : 32 tiles x2 [0,64) ; g_Sigp store [64,256) ---
        if (mm < 64) {
            const int bi = mm >= 32, q = mm & 31;
            FwdS& s = sb[bi];
            const int i0 = 4 * (q >> 2), j0 = 4 * (q & 3);
            float c[4][4] = {};
            #pragma unroll 8
            for (int k = 0; k < NS; ++k) {
                float4 a  = *(const float4*)&s.Sp[k][i0];
                float4 bb = *(const float4*)&s.Ct[k][j0];
                c[0][0] += a.x * bb.x; c[0][1] += a.x * bb.y; c[0][2] += a.x * bb.z; c[0][3] += a.x * bb.w;
                c[1][0] += a.y * bb.x; c[1][1] += a.y * bb.y; c[1][2] += a.y * bb.z; c[1][3] += a.y * bb.w;
                c[2][0] += a.z * bb.x; c[2][1] += a.z * bb.y; c[2][2] += a.z * bb.z; c[2][3] += a.z * bb.w;
                c[3][0] += a.w * bb.x; c[3][1] += a.w * bb.y; c[3][2] += a.w * bb.z; c[3][3] += a.w * bb.w;
            }
            #pragma unroll
            for (int m = 0; m < 4; ++m)
                #pragma unroll
                for (int n = 0; n < 4; ++n) { s.W[i0 + m][j0 + n] = c[m][n]; s.Wt[j0 + n][i0 + m] = c[m][n]; }
        } else {
            const int q2 = mm - 64;
            const int bi = q2 >= 96, e0 = q2 - 96 * bi;
            FwdS& s = sb[bi];
            float* gp = g_Sigp + ((size_t)(b0 + bi) * T + t) * NS * NS;
            for (int e = e0; e < NS * NS; e += 96) gp[e] = s.Sp[e >> 5][e & 31];
        }
        TBAR(bar);

        // --- P4: S = sym(C W)+R : 10 tiles x2 [0,20) ---
        if (mm < 20) {
            const int bi = mm >= 10, q = mm - 10 * bi;
            FwdS& s = sb[bi];
            const int ti = mR4[q], tj = mC4[q];
            const int i0 = 4 * ti, j0 = 4 * tj;
            float c[4][4] = {};
            #pragma unroll 8
            for (int k = 0; k < NS; ++k) {
                float4 a  = *(const float4*)&s.Ct[k][i0];
                float4 bb = *(const float4*)&s.W[k][j0];
                c[0][0] += a.x * bb.x; c[0][1] += a.x * bb.y; c[0][2] += a.x * bb.z; c[0][3] += a.x * bb.w;
                c[1][0] += a.y * bb.x; c[1][1] += a.y * bb.y; c[1][2] += a.y * bb.z; c[1][3] += a.y * bb.w;
                c[2][0] += a.z * bb.x; c[2][1] += a.z * bb.y; c[2][2] += a.z * bb.z; c[2][3] += a.z * bb.w;
                c[3][0] += a.w * bb.x; c[3][1] += a.w * bb.y; c[3][2] += a.w * bb.z; c[3][3] += a.w * bb.w;
            }
            if (ti == tj) {
                #pragma unroll
                for (int m = 0; m < 4; ++m) {
                    c[m][m] += RVAR;
                    #pragma unroll
                    for (int n = m + 1; n < 4; ++n) { float av = 0.5f * (c[m][n] + c[n][m]); c[m][n] = av; c[n][m] = av; }
                }
            }
            #pragma unroll
            for (int m = 0; m < 4; ++m)
                #pragma unroll
                for (int n = 0; n < 4; ++n) {
                    s.S[i0 + m][j0 + n] = c[m][n];
                    if (ti != tj) s.S[j0 + n][i0 + m] = c[m][n];
                }
        }
        TBAR(bar);

        // --- P5: chol16+solve for both batches (warps mm<64) ; prefetch t+1 [64,256) ---
        if (mm < 64) {
            const int bi = mm >= 32;
            FwdS& s = sb[bi];
            const int i = rt & 31;
            float dinv[PD];
            #pragma unroll
            for (int k = 0; k < PD; ++k) {
                float dkk = s.S[k][k];
                float rs  = rsqrtf(dkk);
                dinv[k] = rs;
                __syncwarp();
                if (i == k) s.S[k][k] = dkk * rs;
                if (i > k && i < PD) s.S[i][k] *= rs;
                __syncwarp();
                if (i > k && i < PD) {
                    float lik = s.S[i][k];
                    for (int j2 = k + 1; j2 <= i; ++j2) s.S[i][j2] -= lik * s.S[j2][k];
                }
                __syncwarp();
            }
            {
                float x[PD];
                #pragma unroll
                for (int r2 = 0; r2 < PD; ++r2) {
                    float a0 = s.W[i][r2], a1 = 0.f;
                    #pragma unroll
                    for (int k = 0; k < r2; ++k) {
                        if (k & 1) a1 += s.S[r2][k] * x[k];
                        else       a0 -= s.S[r2][k] * x[k];
                    }
                    x[r2] = (a0 - a1) * dinv[r2];
                }
                #pragma unroll
                for (int r2 = PD - 1; r2 >= 0; --r2) {
                    float a0 = x[r2], a1 = 0.f;
                    #pragma unroll
                    for (int k = r2 + 1; k < PD; ++k) {
                        if (k & 1) a1 += s.S[k][r2] * x[k];
                        else       a0 -= s.S[k][r2] * x[k];
                    }
                    x[r2] = (a0 - a1) * dinv[r2];
                }
                #pragma unroll
                for (int r2 = 0; r2 < PD; ++r2) s.Kt[r2][i] = x[r2];
            }
        } else if (t + 1 < T) {
            const int q = mm - 64;      // 0..191
            for (int bi = 0; bi < 2; ++bi) {
                FwdS& s = sb[bi];
                const size_t bt1 = (size_t)(b0 + bi) * T + t + 1;
                const float* An = A  + bt1 * NS * NS;
                const float* Cn = C  + bt1 * PD * NS;
                const float* Bn = Bm + bt1 * NS * MD;
                for (int e = q; e < NS * NS; e += 192) s.At[e & 31][e >> 5] = An[e];
                for (int e = q; e < PD * NS; e += 192) s.Ct[e & 31][e >> 5] = Cn[e];
                for (int e = q; e < NS * MD; e += 192) s.B[e >> 3][e & 7] = Bn[e];
                if (q < PD) s.y[q] = Y[bt1 * PD + q];
                else if (q < PD + MD) s.uu[q - PD] = U[bt1 * MD + (q - PD)];
            }
        }
        TBAR(bar);

        // --- P6: Sigf = sym(Sp - K W^T) : 36 tiles x2 [0,72) ; mu_f [128,192) ---
        if (mm < 72) {
            const int bi = mm >= 36, q = mm - 36 * bi;
            FwdS& s = sb[bi];
            const size_t bt = (size_t)(b0 + bi) * T + t;
            float* gf = g_Sigf + bt * NS * NS;
            float* ob = out + bt * (size_t)(NS * (NS + 1));
            const int ti = mR8[q], tj = mC8[q];
            const int i0 = 4 * ti, j0 = 4 * tj;
            float c[4][4];
            #pragma unroll
            for (int m = 0; m < 4; ++m) {
                float4 sp = *(const float4*)&s.Sp[i0 + m][j0];
                c[m][0] = sp.x; c[m][1] = sp.y; c[m][2] = sp.z; c[m][3] = sp.w;
            }
            #pragma unroll
            for (int k = 0; k < PD; ++k) {
                float4 a  = *(const float4*)&s.Kt[k][i0];
                float4 bb = *(const float4*)&s.Wt[k][j0];
                c[0][0] -= a.x * bb.x; c[0][1] -= a.x * bb.y; c[0][2] -= a.x * bb.z; c[0][3] -= a.x * bb.w;
                c[1][0] -= a.y * bb.x; c[1][1] -= a.y * bb.y; c[1][2] -= a.y * bb.z; c[1][3] -= a.y * bb.w;
                c[2][0] -= a.z * bb.x; c[2][1] -= a.z * bb.y; c[2][2] -= a.z * bb.z; c[2][3] -= a.z * bb.w;
                c[3][0] -= a.w * bb.x; c[3][1] -= a.w * bb.y; c[3][2] -= a.w * bb.z; c[3][3] -= a.w * bb.w;
            }
            if (ti == tj) {
                #pragma unroll
                for (int m = 0; m < 4; ++m)
                    #pragma unroll
                    for (int n = m + 1; n < 4; ++n) { float av = 0.5f * (c[m][n] + c[n][m]); c[m][n] = av; c[n][m] = av; }
            }
            #pragma unroll
            for (int m = 0; m < 4; ++m)
                #pragma unroll
                for (int n = 0; n < 4; ++n) {
                    s.Sig[i0 + m][j0 + n] = c[m][n];
                    gf[(i0 + m) * NS + j0 + n] = c[m][n];
                    if (t == T - 1) ob[(i0 + m) * (NS + 1) + 1 + j0 + n] = c[m][n];
                    if (ti != tj) {
                        s.Sig[j0 + n][i0 + m] = c[m][n];
                        gf[(j0 + n) * NS + i0 + m] = c[m][n];
                        if (t == T - 1) ob[(j0 + n) * (NS + 1) + 1 + i0 + m] = c[m][n];
                    }
                }
        } else if (mm >= 128 && mm < 192) {
            const int bi = (mm - 128) >> 5, i = mm & 31;
            FwdS& s = sb[bi];
            const size_t bt = (size_t)(b0 + bi) * T + t;
            float acc = s.mup[i];
            #pragma unroll
            for (int k = 0; k < PD; ++k) acc += s.Kt[k][i] * s.r[k];
            s.mu[i] = acc;
            g_muf[bt * NS + i] = acc;
            if (t == T - 1) out[bt * (size_t)(NS * (NS + 1)) + i * (NS + 1)] = acc;
        }
        TBAR(bar);
    }
}

// ============================ J PRECOMPUTE (fully parallel) ============================
__global__ __launch_bounds__(32, 1)
void jpre_kernel(const float* __restrict__ A)
{
    __shared__ __align__(16) float sl[NS][33];
    const int lane = threadIdx.x;
    const int b = blockIdx.x;
    const int t = blockIdx.y;
    const size_t bt = (size_t)b * T + t;
    const float* Ag  = A      + bt * NS * NS;
    const float* Sfg = g_Sigf + bt * NS * NS;
    const float* Spg = g_Sigp + (bt + 1) * NS * NS;

    #pragma unroll
    for (int e = lane; e < NS * NS / 4; e += 32) {
        float4 v = ((const float4*)Ag)[e];
        int r = (4 * e) >> 5, c = (4 * e) & 31;
        sl[r][c] = v.x; sl[r][c + 1] = v.y; sl[r][c + 2] = v.z; sl[r][c + 3] = v.w;
    }
    float sf[NS];
    #pragma unroll
    for (int q = 0; q < 8; ++q) {
        float4 v = ((const float4*)(Sfg + lane * NS))[q];
        sf[4 * q] = v.x; sf[4 * q + 1] = v.y; sf[4 * q + 2] = v.z; sf[4 * q + 3] = v.w;
    }
    __syncwarp();
    float m[NS];
    #pragma unroll
    for (int r = 0; r < NS; ++r) {
        float a0 = 0.f, a1 = 0.f;
        #pragma unroll 8
        for (int k = 0; k < NS; k += 2) { a0 += sf[k] * sl[r][k]; a1 += sf[k + 1] * sl[r][k + 1]; }
        m[r] = a0 + a1;
    }
    __syncwarp();
    #pragma unroll
    for (int e = lane; e < NS * NS / 4; e += 32) {
        float4 v = ((const float4*)Spg)[e];
        int r = (4 * e) >> 5, c = (4 * e) & 31;
        sl[r][c] = v.x; sl[r][c + 1] = v.y; sl[r][c + 2] = v.z; sl[r][c + 3] = v.w;
    }
    __syncwarp();
    {
        const int i = lane;
        #pragma unroll 1
        for (int k = 0; k < NS; ++k) {
            float dkk = sl[k][k];
            float rs  = rsqrtf(dkk);
            __syncwarp();
            if (i == k) { sl[k][k] = dkk * rs; sl[k][32] = rs; }
            if (i > k) sl[i][k] *= rs;
            __syncwarp();
            if (i > k) {
                float lik = sl[i][k];
                for (int j2 = k + 1; j2 <= i; ++j2) sl[i][j2] -= lik * sl[j2][k];
            }
            __syncwarp();
        }
    }
    float x[NS];
    #pragma unroll
    for (int r = 0; r < NS; ++r) {
        float a0 = m[r], a1 = 0.f;
        #pragma unroll
        for (int k = 0; k < r; ++k) {
            if (k & 1) a1 += sl[r][k] * x[k];
            else       a0 -= sl[r][k] * x[k];
        }
        x[r] = (a0 - a1) * sl[r][32];
    }
    #pragma unroll
    for (int r = NS - 1; r >= 0; --r) {
        float a0 = x[r], a1 = 0.f;
        #pragma unroll
        for (int k = r + 1; k < NS; ++k) {
            if (k & 1) a1 += sl[k][r] * x[k];
            else       a0 -= sl[k][r] * x[k];
        }
        x[r] = (a0 - a1) * sl[r][32];
    }
    float* Jg = g_J + bt * NS * NS;
    #pragma unroll
    for (int k = 0; k < NS; ++k) Jg[k * NS + lane] = x[k];
}

// ============== BACKWARD SMOOTHER (2 teams/CTA, 2 batches/team, 4x4 tiles) ==============
__global__ __launch_bounds__(512, 1)
void bwd_kernel(float* __restrict__ out)
{
    extern __shared__ __align__(16) char dyn[];
    __shared__ unsigned char mR8[36], mC8[36];

    const int tid  = threadIdx.x;
    const int team = tid >> 8, rt = tid & 255;
    const int bar  = 1 + team;
    BwdS* sb = (BwdS*)dyn + team * 2;
    const int b0 = blockIdx.x * 4 + team * 2;
    const int mm = team ? (rt ^ 64) : rt;

    if (tid == 0) {
        int e = 0;
        for (int r = 0; r < 8; ++r)
            for (int c = r; c < 8; ++c) { mR8[e] = (unsigned char)r; mC8[e] = (unsigned char)c; ++e; }
    }
    for (int bi = 0; bi < 2; ++bi) {
        BwdS& s = sb[bi];
        const int t0 = T - 2, p0 = t0 & 1;
        const size_t bt  = (size_t)(b0 + bi) * T + t0;
        const size_t btL = (size_t)(b0 + bi) * T + (T - 1);
        const float* Sfg = g_Sigf + bt * NS * NS;
        const float* Spg = g_Sigp + (bt + 1) * NS * NS;
        const float* Jg  = g_J    + bt * NS * NS;
        const float* SfL = g_Sigf + btL * NS * NS;
        for (int e = rt; e < NS * NS; e += 256) {
            s.Sf[p0][e >> 5][e & 31] = Sfg[e];
            s.Sp[p0][e >> 5][e & 31] = Spg[e];
            s.Jt[p0][e >> 5][e & 31] = Jg[e];
            s.Sig[e >> 5][e & 31]    = SfL[e];
        }
        if (rt < NS) { s.mufB[p0][rt] = g_muf[bt * NS + rt]; s.muP[(T - 1) & 1][rt] = g_muf[btL * NS + rt]; }
        else if (rt < 2 * NS) s.mupB[p0][rt - NS] = g_mup[(bt + 1) * NS + (rt - NS)];
    }
    __syncthreads();

    for (int t = T - 2; t >= 0; --t) {
        const int p = t & 1;

        // phaseA: T1^T = (J (Sig_s - Sp))^T : 64 tiles x2 [0,128)
        if (mm < 128) {
            const int bi = mm >> 6, q = mm & 63;
            BwdS& s = sb[bi];
            float (*Jt)[ST] = s.Jt[p];
            float (*Sp)[ST] = s.Sp[p];
            const int i0 = 4 * (q >> 3), j0 = 4 * (q & 7);
            float c[4][4] = {};
            #pragma unroll 8
            for (int k = 0; k < NS; ++k) {
                float4 a  = *(const float4*)&Jt[k][i0];
                float4 s1 = *(const float4*)&s.Sig[k][j0];
                float4 s2 = *(const float4*)&Sp[k][j0];
                float bx = s1.x - s2.x, by = s1.y - s2.y, bz = s1.z - s2.z, bw = s1.w - s2.w;
                c[0][0] += a.x * bx; c[0][1] += a.x * by; c[0][2] += a.x * bz; c[0][3] += a.x * bw;
                c[1][0] += a.y * bx; c[1][1] += a.y * by; c[1][2] += a.y * bz; c[1][3] += a.y * bw;
                c[2][0] += a.z * bx; c[2][1] += a.z * by; c[2][2] += a.z * bz; c[2][3] += a.z * bw;
                c[3][0] += a.w * bx; c[3][1] += a.w * by; c[3][2] += a.w * bz; c[3][3] += a.w * bw;
            }
            #pragma unroll
            for (int m = 0; m < 4; ++m)
                #pragma unroll
                for (int n = 0; n < 4; ++n) s.T1[j0 + n][i0 + m] = c[m][n];
        }
        TBAR(bar);

        // phaseB: Sig_n 36x2 [0,72) ; mu_n [72,136) ; prefetch t-1 [136,256)
        if (mm < 72) {
            const int bi = mm >= 36, q = mm - 36 * bi;
            BwdS& s = sb[bi];
            float (*Jt)[ST] = s.Jt[p];
            float (*Sf)[ST] = s.Sf[p];
            float* ob = out + ((size_t)(b0 + bi) * T + t) * (size_t)(NS * (NS + 1));
            const int ti = mR8[q], tj = mC8[q];
            const int i0 = 4 * ti, j0 = 4 * tj;
            float c[4][4];
            #pragma unroll
            for (int m = 0; m < 4; ++m) {
                float4 sfv = *(const float4*)&Sf[i0 + m][j0];
                c[m][0] = sfv.x; c[m][1] = sfv.y; c[m][2] = sfv.z; c[m][3] = sfv.w;
            }
            #pragma unroll 8
            for (int k = 0; k < NS; ++k) {
                float4 a  = *(const float4*)&s.T1[k][i0];
                float4 bb = *(const float4*)&Jt[k][j0];
                c[0][0] += a.x * bb.x; c[0][1] += a.x * bb.y; c[0][2] += a.x * bb.z; c[0][3] += a.x * bb.w;
                c[1][0] += a.y * bb.x; c[1][1] += a.y * bb.y; c[1][2] += a.y * bb.z; c[1][3] += a.y * bb.w;
                c[2][0] += a.z * bb.x; c[2][1] += a.z * bb.y; c[2][2] += a.z * bb.z; c[2][3] += a.z * bb.w;
                c[3][0] += a.w * bb.x; c[3][1] += a.w * bb.y; c[3][2] += a.w * bb.z; c[3][3] += a.w * bb.w;
            }
            if (ti == tj) {
                #pragma unroll
                for (int m = 0; m < 4; ++m)
                    #pragma unroll
                    for (int n = m + 1; n < 4; ++n) { float av = 0.5f * (c[m][n] + c[n][m]); c[m][n] = av; c[n][m] = av; }
            }
            #pragma unroll
            for (int m = 0; m < 4; ++m)
                #pragma unroll
                for (int n = 0; n < 4; ++n) {
                    s.Sig[i0 + m][j0 + n] = c[m][n];
                    ob[(i0 + m) * (NS + 1) + 1 + j0 + n] = c[m][n];
                    if (ti != tj) {
                        s.Sig[j0 + n][i0 + m] = c[m][n];
                        ob[(j0 + n) * (NS + 1) + 1 + i0 + m] = c[m][n];
                    }
                }
        } else if (mm < 136) {
            const int q2 = mm - 72;
            const int bi = q2 >= 32, i = q2 & 31;
            BwdS& s = sb[bi];
            float (*Jt)[ST] = s.Jt[p];
            float acc = s.mufB[p][i];
            #pragma unroll 8
            for (int k = 0; k < NS; ++k) acc += Jt[k][i] * (s.muP[p ^ 1][k] - s.mupB[p][k]);
            s.muP[p][i] = acc;
            out[((size_t)(b0 + bi) * T + t) * (size_t)(NS * (NS + 1)) + i * (NS + 1)] = acc;
        } else if (t > 0) {
            const int q2 = mm - 136;           // 0..119
            const int bi = q2 >= 60, e0 = q2 - 60 * bi;
            BwdS& s = sb[bi];
            const size_t bt  = (size_t)(b0 + bi) * T + t;
            const size_t btm = bt - 1;
            const float* Sfg = g_Sigf + btm * NS * NS;
            const float* Spg = g_Sigp + bt * NS * NS;
            const float* Jg  = g_J    + btm * NS * NS;
            const int pn = p ^ 1;
            for (int e = e0; e < NS * NS; e += 60) {
                s.Sf[pn][e >> 5][e & 31] = Sfg[e];
                s.Sp[pn][e >> 5][e & 31] = Spg[e];
                s.Jt[pn][e >> 5][e & 31] = Jg[e];
            }
            for (int e = e0; e < 2 * NS; e += 60) {
                if (e < NS) s.mufB[pn][e] = g_muf[btm * NS + e];
                else        s.mupB[pn][e - NS] = g_mup[bt * NS + (e - NS)];
            }
        }
        TBAR(bar);
    }
}

extern "C" void kernel_launch(void* const* d_in, const int* in_sizes, int n_in,
                              void* d_out, int out_size)
{
    const float* Y    = (const float*)d_in[0];
    const float* U    = (const float*)d_in[1];
    const float* A    = (const float*)d_in[2];
    const float* Bm   = (const float*)d_in[3];
    const float* C    = (const float*)d_in[4];
    const float* mu0  = (const float*)d_in[5];
    const float* Sig0 = (const float*)d_in[6];
    float* out = (float*)d_out;

    cudaFuncSetAttribute(fwd_kernel, cudaFuncAttributeMaxDynamicSharedMemorySize,
                         (int)(4 * sizeof(FwdS)));
    cudaFuncSetAttribute(bwd_kernel, cudaFuncAttributeMaxDynamicSharedMemorySize,
                         (int)(4 * sizeof(BwdS)));

    fwd_kernel<<<BATCH / 4, 512, 4 * sizeof(FwdS)>>>(Y, U, A, Bm, C, mu0, Sig0, out);
    jpre_kernel<<<dim3(BATCH, T - 1), 32>>>(A);
    bwd_kernel<<<BATCH / 4, 512, 4 * sizeof(BwdS)>>>(out);
}